// round 14
// baseline (speedup 1.0000x reference)
#include <cuda_runtime.h>
#include <cuda_bf16.h>
#include <cuda_fp16.h>
#include <cstdint>

#define H_ 4
#define N_ 4096
#define D_ 128
#define KX_ 512            // H * D
#define NW_ (N_/32)        // 128 mask words per row
#define ALPHA_ 0.2f

// ---------------- device scratch (uint4-backed for 16B alignment) --------
__device__ unsigned g_adjb[N_*NW_];          // 2 MB adjacency bitmask
__device__ float2   g_EFs[H_*N_];            // rows: {e^s, e^.2s}
__device__ float2   g_EFd[H_*N_];            // cols: {e^d, e^.2d}
__device__ uint4    g_whT4[H_*D_*N_/8];      // Wh^T (fp16) [h][f][j]
__device__ uint4    g_ch4 [H_*N_*D_/8];      // chems (fp16)
__device__ uint4    g_x4  [N_*KX_/8];        // stage-1 output (fp16)
__device__ uint4    g_W1T4[H_*D_*D_/8];      // W1^T (fp16) [h][dout][k]
__device__ uint4    g_W2T4[H_*D_*KX_/8];     // W2^T (fp16) [h][dout][k]

#define g_whT ((__half*)g_whT4)
#define g_ch  ((__half*)g_ch4)
#define g_x   ((__half*)g_x4)
#define g_W1T ((__half*)g_W1T4)
#define g_W2T ((__half*)g_W2T4)

// ---------------- helpers ----------------
__device__ __forceinline__ uint32_t smem_u32(const void* p){
    uint32_t a;
    asm("{ .reg .u64 t; cvta.to.shared.u64 t, %1; cvt.u32.u64 %0, t; }"
        : "=r"(a) : "l"(p));
    return a;
}
#define SW128(o) ((o) ^ (((o) >> 3) & 0x70))

#define BAR_SYNC(id)   asm volatile("bar.sync %0, 768;"   :: "r"(id) : "memory")
#define BAR_ARRIVE(id) asm volatile("bar.arrive %0, 768;" :: "r"(id) : "memory")

__device__ __forceinline__ float eluf(float x){ return x > 0.f ? x : expm1f(x); }

__device__ __forceinline__ float fexp(float x){
    const float L2E   = 1.4426950408889634f;
    const float MAGIC = 12582912.0f;
    float t  = x * L2E;
    float kf = t + MAGIC;
    int   ki = __float_as_int(kf);
    float km = kf - MAGIC;
    float f  = t - km;
    float p  = 1.33335581e-3f;
    p = fmaf(p, f, 9.61812910e-3f);
    p = fmaf(p, f, 5.55041087e-2f);
    p = fmaf(p, f, 2.40226507e-1f);
    p = fmaf(p, f, 6.93147180e-1f);
    p = fmaf(p, f, 1.0f);
    return __int_as_float(__float_as_int(p) + (int)((unsigned)ki << 23));
}

__device__ __forceinline__ void ldsm4(uint32_t* r, uint32_t addr){
    asm volatile("ldmatrix.sync.aligned.m8n8.x4.shared.b16 {%0,%1,%2,%3}, [%4];"
        : "=r"(r[0]),"=r"(r[1]),"=r"(r[2]),"=r"(r[3]) : "r"(addr));
}
__device__ __forceinline__ void mma16816h(float* c, const uint32_t* a, const uint32_t* b){
    asm volatile("mma.sync.aligned.m16n8k16.row.col.f32.f16.f16.f32 "
        "{%0,%1,%2,%3}, {%4,%5,%6,%7}, {%8,%9}, {%0,%1,%2,%3};"
        : "+f"(c[0]),"+f"(c[1]),"+f"(c[2]),"+f"(c[3])
        : "r"(a[0]),"r"(a[1]),"r"(a[2]),"r"(a[3]), "r"(b[0]),"r"(b[1]));
}
__device__ __forceinline__ void cpasync16(uint32_t dst, const void* src){
    asm volatile("cp.async.cg.shared.global [%0], [%1], 16;" :: "r"(dst), "l"(src));
}
#define CP_COMMIT() asm volatile("cp.async.commit_group;" ::: "memory")
#define CP_WAIT0()  asm volatile("cp.async.wait_group 0;"  ::: "memory")

// ---------------- K0: pack adj ----------------
__global__ void pack_adj(const int* __restrict__ adj) {
    int gwarp  = (blockIdx.x*blockDim.x + threadIdx.x) >> 5;
    int lane   = threadIdx.x & 31;
    int nwarps = (gridDim.x*blockDim.x) >> 5;
    for (int w = gwarp; w < N_*NW_; w += nwarps) {
        int v = adj[(size_t)w*32 + lane];
        unsigned bits = __ballot_sync(0xffffffffu, v > 0);
        if (lane == 0) g_adjb[w] = bits;
    }
}

// ---------------- K0b: chems -> fp16 ----------------
__global__ void split_ch(const float* __restrict__ c){
    size_t i = ((size_t)blockIdx.x*blockDim.x + threadIdx.x)*4;
    float4 v = *(const float4*)(c + i);
    __half2 h0 = __floats2half2_rn(v.x, v.y);
    __half2 h1 = __floats2half2_rn(v.z, v.w);
    uint2 o = make_uint2(*(uint32_t*)&h0, *(uint32_t*)&h1);
    *(uint2*)((char*)g_ch + i*2) = o;
}

// ---------------- K0c: W [h][K][128] -> W^T fp16 [h][128][K] ----------
__global__ void split_WT(const float* __restrict__ W, int K, int which){
    __shared__ float ts[32][33];
    __half* T = (which==1) ? g_W1T : g_W2T;
    int h = blockIdx.z, k0 = blockIdx.x*32, f0 = blockIdx.y*32;
    int tx = threadIdx.x & 31, ty = threadIdx.x >> 5;
    const float* Wh = W + (size_t)h*K*128;
    #pragma unroll
    for (int r=0;r<4;r++)
        ts[ty + r*8][tx] = Wh[(size_t)(k0 + ty + r*8)*128 + f0 + tx];
    __syncthreads();
    #pragma unroll
    for (int r=0;r<4;r++){
        int f = f0 + ty + r*8;
        float v = ts[tx][ty + r*8];
        T[((size_t)h*128 + f)*K + k0 + tx] = __float2half_rn(v);
    }
}

// ---------------- K1: Wh = X @ W, single-term fp16, fused epilogue -------
#define GA    0
#define GB    32768
#define ETT   0
#define ERED  36864
#define SMEMG (65536 + 1024)

__global__ __launch_bounds__(256,1) void gemm_hmma(int stage, int K,
                                                   const float* __restrict__ avec)
{
    extern __shared__ char dsm[];
    uint32_t raw = smem_u32(dsm);
    uint32_t sb  = (raw + 1023) & ~1023u;
    char* bpp = dsm + (sb - raw);

    const __half *A, *BT;
    long aHeadStride;
    if (stage == 1){ A = g_ch; BT = g_W1T; aHeadStride = (long)N_*D_; }
    else           { A = g_x;  BT = g_W2T; aHeadStride = 0; }

    int h = blockIdx.y, m0 = blockIdx.x*128;
    int tid = threadIdx.x, lane = tid & 31, wid = tid >> 5;
    int wm = wid >> 2, wn = wid & 3;
    const char* pA = (const char*)(A + (size_t)h*aHeadStride + (size_t)m0*K);
    const char* pB = (const char*)(BT + (size_t)h*128*K);
    long rs = (long)K*2;

    float acc[4][4][4];
    #pragma unroll
    for (int a=0;a<4;a++)
        #pragma unroll
        for (int b=0;b<4;b++)
            #pragma unroll
            for (int c=0;c<4;c++) acc[a][b][c]=0.f;

    auto ldpart = [&](uint32_t dstBase, const char* g, long colByte){
        #pragma unroll
        for (int l=0;l<8;l++){
            int idx = tid + l*256;
            int row = idx >> 4;
            int s16 = idx & 15;
            uint32_t so = SW128((uint32_t)(row*128 + (s16&7)*16)) + (uint32_t)(s16>>3)*16384;
            cpasync16(sb + dstBase + so, g + (long)row*rs + colByte + s16*16);
        }
    };

    int nk = K >> 7;
    for (int kc = 0; kc < nk; ++kc){
        long cb = (long)kc*256;
        ldpart(GA, pA, cb);
        ldpart(GB, pB, cb);
        CP_COMMIT();
        CP_WAIT0();
        __syncthreads();
        #pragma unroll
        for (int kt=0;kt<8;kt++){
            uint32_t subo = (uint32_t)(kt>>2)*16384;
            uint32_t kb = (uint32_t)((kt&3)*32 + (lane>>4)*16);
            uint32_t bh[4][2];
            #pragma unroll
            for (int pp=0;pp<2;pp++){
                uint32_t off = SW128((uint32_t)((wn*32 + pp*16 + (lane&15))*128) + kb) + subo;
                uint32_t t0[4];
                ldsm4(t0, sb + GB + off);
                bh[pp*2  ][0]=t0[0]; bh[pp*2  ][1]=t0[2];
                bh[pp*2+1][0]=t0[1]; bh[pp*2+1][1]=t0[3];
            }
            #pragma unroll
            for (int mt=0;mt<4;mt++){
                uint32_t off = SW128((uint32_t)((wm*64 + mt*16 + (lane&15))*128) + kb) + subo;
                uint32_t ah[4];
                ldsm4(ah, sb + GA + off);
                #pragma unroll
                for (int nt=0;nt<4;nt++)
                    mma16816h(acc[mt][nt], ah, bh[nt]);
            }
        }
        __syncthreads();
    }

    // ---------------- fused epilogue ----------------
    __half* tT   = (__half*)(bpp + ETT);
    float*  sred = (float*)(bpp + ERED);
    const float* av = avec + h*2*D_;

    float sp[8], dp[8];
    #pragma unroll
    for (int i=0;i<8;i++){ sp[i]=0.f; dp[i]=0.f; }

    #pragma unroll
    for (int nt=0;nt<4;nt++){
        int fcol = wn*32 + nt*8 + (lane&3)*2;
        float as0 = av[fcol],       as1 = av[fcol+1];
        float ad0 = av[D_+fcol],    ad1 = av[D_+fcol+1];
        #pragma unroll
        for (int mt=0;mt<4;mt++){
            int r0l = wm*64 + mt*16 + (lane>>2);
            float c0 = acc[mt][nt][0], c1 = acc[mt][nt][1];
            float c2 = acc[mt][nt][2], c3 = acc[mt][nt][3];
            sp[mt*2  ] += c0*as0 + c1*as1;
            sp[mt*2+1] += c2*as0 + c3*as1;
            dp[mt*2  ] += c0*ad0 + c1*ad1;
            dp[mt*2+1] += c2*ad0 + c3*ad1;
            tT[(size_t)fcol*136     + r0l    ] = __float2half_rn(c0);
            tT[(size_t)(fcol+1)*136 + r0l    ] = __float2half_rn(c1);
            tT[(size_t)fcol*136     + r0l + 8] = __float2half_rn(c2);
            tT[(size_t)(fcol+1)*136 + r0l + 8] = __float2half_rn(c3);
        }
    }
    #pragma unroll
    for (int k=1;k<4;k<<=1){
        #pragma unroll
        for (int i=0;i<8;i++){
            sp[i] += __shfl_xor_sync(0xffffffffu, sp[i], k);
            dp[i] += __shfl_xor_sync(0xffffffffu, dp[i], k);
        }
    }
    if ((lane & 3) == 0){
        #pragma unroll
        for (int mt=0;mt<4;mt++){
            int r0l = wm*64 + mt*16 + (lane>>2);
            sred[0*512 + wn*128 + r0l    ] = sp[mt*2];
            sred[0*512 + wn*128 + r0l + 8] = sp[mt*2+1];
            sred[1*512 + wn*128 + r0l    ] = dp[mt*2];
            sred[1*512 + wn*128 + r0l + 8] = dp[mt*2+1];
        }
    }
    __syncthreads();
    if (tid < 128){
        float s = sred[0*512 + tid] + sred[0*512 + 128 + tid]
                + sred[0*512 + 256 + tid] + sred[0*512 + 384 + tid];
        float d = sred[1*512 + tid] + sred[1*512 + 128 + tid]
                + sred[1*512 + 256 + tid] + sred[1*512 + 384 + tid];
        int i = m0 + tid;
        g_EFs[h*N_+i] = make_float2(fexp(s), fexp(ALPHA_*s));
        g_EFd[h*N_+i] = make_float2(fexp(d), fexp(ALPHA_*d));
    }
    {
        int f = tid >> 1, half = tid & 1;
        const uint4* src = (const uint4*)((const char*)tT + (size_t)f*272 + half*128);
        uint4* dst = (uint4*)(g_whT + ((size_t)(h*D_ + f))*N_ + m0 + half*64);
        #pragma unroll
        for (int q=0;q<8;q++) dst[q] = src[q];
    }
}

// ---------------- K3: attn, 16 consumer + 8 producer warps ---------------
// barriers: full[s]=1+s, empty[s]=4+s (s=0..2), sml=7; count 768
// consumers wid 0-15: warp tile 32x32 (wm=wid>>2 rows, wn=wid&3 cols)
// producers wid 16-23: identical to R13 producer code
#define PB    0
#define WB    16384
#define BUFSZ 32768
#define NBUF  3
#define OFF_L (NBUF*BUFSZ)
#define SMEM_DYN (NBUF*BUFSZ + 512 + 1024)

__global__ __launch_bounds__(768,1) void attn_hmma(float* __restrict__ out_ext, int stage) {
    extern __shared__ char dsm[];
    uint32_t raw = smem_u32(dsm);
    uint32_t sb  = (raw + 1023) & ~1023u;
    char* bp = dsm + (sb - raw);
    float* sml = (float*)(bp + OFF_L);

    int h = blockIdx.y, i0 = blockIdx.x*128;
    int tid = threadIdx.x, lane = tid & 31, wid = tid >> 5;
    bool producer = (wid >= 16);

    if (producer) {
        int ptid = tid - 512;
        int r = ptid >> 1, jh = ptid & 1;
        float2 efs = g_EFs[h*N_ + i0 + r];
        float Ei = efs.x, Fi = efs.y;
        const float2*   efd    = g_EFd + h*N_;
        const unsigned* adjrow = g_adjb + (size_t)(i0+r)*NW_;
        const char* whh = (const char*)(g_whT + (size_t)h*D_*N_);
        float rsum = 0.f;

        auto loadW = [&](uint32_t tb, int c){
            int j0 = c * 64;
            #pragma unroll
            for (int l=0;l<4;l++){
                int idx = ptid + l*256;
                int f = idx >> 3, seg = idx & 7;
                size_t go = (((size_t)f*N_ + j0) << 1) + (size_t)seg*16;
                uint32_t so = SW128((uint32_t)(f*128 + seg*16));
                cpasync16(sb + tb + WB + so, whh + go);
            }
            CP_COMMIT();
        };
        auto genP = [&](uint32_t tb, int c){
            int j0 = c * 64;
            unsigned w = adjrow[(j0>>5) + jh];
            const float4* efp = (const float4*)(efd + j0 + jh*32);
            uint32_t rb = (uint32_t)(r*128 + jh*64);
            #pragma unroll
            for (int q=0;q<16;q++){
                float4 e01 = efp[q];
                float p0 = fmaxf(Ei*e01.x, Fi*e01.y);
                float p1 = fmaxf(Ei*e01.z, Fi*e01.w);
                p0 = ((w>>(2*q  ))&1u) ? p0 : 0.f;
                p1 = ((w>>(2*q+1))&1u) ? p1 : 0.f;
                rsum += p0 + p1;
                __half2 hp = __floats2half2_rn(p0, p1);
                *(uint32_t*)(bp + tb + PB + SW128(rb + q*4)) = *(uint32_t*)&hp;
            }
        };

        int s = 0;
        for (int c = 0; c < 64; ++c) {
            uint32_t tb = (uint32_t)s << 15;
            if (c >= NBUF) BAR_SYNC(4 + s);
            loadW(tb, c);
            genP(tb, c);
            CP_WAIT0();
            BAR_ARRIVE(1 + s);
            if (++s == NBUF) s = 0;
        }
        float full = rsum + __shfl_xor_sync(0xffffffffu, rsum, 1);
        if (!(ptid & 1)) sml[r] = 1.0f / full;
        BAR_ARRIVE(7);
    } else {
        int wm = wid >> 2, wn = wid & 3;          // 4x4 warp grid, 32x32 tiles
        float acc[2][4][4];
        #pragma unroll
        for (int a=0;a<2;a++)
            #pragma unroll
            for (int b=0;b<4;b++)
                #pragma unroll
                for (int c=0;c<4;c++) acc[a][b][c]=0.f;

        int s = 0;
        for (int c = 0; c < 64; ++c) {
            uint32_t tb = (uint32_t)s << 15;
            BAR_SYNC(1 + s);
            #pragma unroll
            for (int kt=0;kt<4;kt++){
                uint32_t kb = (uint32_t)(kt*32 + (lane>>4)*16);
                uint32_t bh[4][2];
                #pragma unroll
                for (int pp=0;pp<2;pp++){
                    uint32_t off = SW128((uint32_t)((wn*32 + pp*16 + (lane&15))*128) + kb);
                    uint32_t t0[4];
                    ldsm4(t0, sb + tb + WB + off);
                    bh[pp*2  ][0]=t0[0]; bh[pp*2  ][1]=t0[2];
                    bh[pp*2+1][0]=t0[1]; bh[pp*2+1][1]=t0[3];
                }
                #pragma unroll
                for (int mt=0;mt<2;mt++){
                    uint32_t off = SW128((uint32_t)((wm*32 + mt*16 + (lane&15))*128) + kb);
                    uint32_t ah[4];
                    ldsm4(ah, sb + tb + PB + off);
                    #pragma unroll
                    for (int nt=0;nt<4;nt++)
                        mma16816h(acc[mt][nt], ah, bh[nt]);
                }
            }
            BAR_ARRIVE(4 + s);
            if (++s == NBUF) s = 0;
        }
        BAR_SYNC(7);                              // sml ready
        #pragma unroll
        for (int mt=0;mt<2;mt++){
            int r0 = wm*32 + mt*16 + (lane>>2);
            float il0 = sml[r0], il1 = sml[r0+8];
            #pragma unroll
            for (int nt=0;nt<4;nt++){
                int fcol = wn*32 + nt*8 + (lane&3)*2;
                float2 v0, v1;
                v0.x = eluf(acc[mt][nt][0]*il0);
                v0.y = eluf(acc[mt][nt][1]*il0);
                v1.x = eluf(acc[mt][nt][2]*il1);
                v1.y = eluf(acc[mt][nt][3]*il1);
                if (stage == 1){
                    size_t o0 = ((size_t)(i0+r0  )*KX_ + h*D_ + fcol);
                    size_t o1 = ((size_t)(i0+r0+8)*KX_ + h*D_ + fcol);
                    __half2 x0 = __floats2half2_rn(v0.x, v0.y);
                    __half2 x1 = __floats2half2_rn(v1.x, v1.y);
                    *(uint32_t*)((char*)g_x + o0*2) = *(uint32_t*)&x0;
                    *(uint32_t*)((char*)g_x + o1*2) = *(uint32_t*)&x1;
                } else {
                    *(float2*)(out_ext + (size_t)(i0+r0  )*KX_ + h*D_ + fcol) = v0;
                    *(float2*)(out_ext + (size_t)(i0+r0+8)*KX_ + h*D_ + fcol) = v1;
                }
            }
        }
    }
}

// ---------------- launch ----------------
extern "C" void kernel_launch(void* const* d_in, const int* in_sizes, int n_in,
                              void* d_out, int out_size) {
    const float* chems = (const float*)d_in[0];
    const int*   adj   = (const int*)  d_in[1];
    const float* W1    = (const float*)d_in[2];
    const float* a1    = (const float*)d_in[3];
    const float* W2    = (const float*)d_in[4];
    const float* a2    = (const float*)d_in[5];
    float* out = (float*)d_out;

    cudaFuncSetAttribute(attn_hmma, cudaFuncAttributeMaxDynamicSharedMemorySize, SMEM_DYN);
    cudaFuncSetAttribute(gemm_hmma, cudaFuncAttributeMaxDynamicSharedMemorySize, SMEMG);

    pack_adj<<<1024, 256>>>(adj);
    split_ch<<<H_*N_*D_/1024, 256>>>(chems);
    split_WT<<<dim3(4, 4, H_), 256>>>(W1, 128, 1);
    split_WT<<<dim3(16, 4, H_), 256>>>(W2, 512, 2);

    // stage 1 (gemm fuses Wh^T conversion + src/dst exp factors)
    gemm_hmma<<<dim3(N_/128, H_), 256, SMEMG>>>(1, 128, a1);
    attn_hmma<<<dim3(N_/128, H_), 768, SMEM_DYN>>>(nullptr, 1);

    // stage 2
    gemm_hmma<<<dim3(N_/128, H_), 256, SMEMG>>>(2, 512, a2);
    attn_hmma<<<dim3(N_/128, H_), 768, SMEM_DYN>>>(out, 2);
}

// round 15
// speedup vs baseline: 1.0688x; 1.0688x over previous
#include <cuda_runtime.h>
#include <cuda_bf16.h>
#include <cuda_fp16.h>
#include <cstdint>

#define H_ 4
#define N_ 4096
#define D_ 128
#define KX_ 512            // H * D
#define NW_ (N_/32)        // 128 mask words per row
#define ALPHA_ 0.2f

// ---------------- device scratch (uint4-backed for 16B alignment) --------
__device__ unsigned g_adjb[N_*NW_];          // 2 MB adjacency bitmask
__device__ float2   g_EFs[H_*N_];            // rows: {e^s, e^.2s}
__device__ float2   g_EFd[H_*N_];            // cols: {e^d, e^.2d}
__device__ uint4    g_whT4[H_*D_*N_/8];      // Wh^T (fp16) [h][f][j]
__device__ uint4    g_ch4 [H_*N_*D_/8];      // chems (fp16)
__device__ uint4    g_x4  [N_*KX_/8];        // stage-1 output (fp16)
__device__ uint4    g_W1T4[H_*D_*D_/8];      // W1^T (fp16) [h][dout][k]
__device__ uint4    g_W2T4[H_*D_*KX_/8];     // W2^T (fp16) [h][dout][k]

#define g_whT ((__half*)g_whT4)
#define g_ch  ((__half*)g_ch4)
#define g_x   ((__half*)g_x4)
#define g_W1T ((__half*)g_W1T4)
#define g_W2T ((__half*)g_W2T4)

// ---------------- helpers ----------------
__device__ __forceinline__ uint32_t smem_u32(const void* p){
    uint32_t a;
    asm("{ .reg .u64 t; cvta.to.shared.u64 t, %1; cvt.u32.u64 %0, t; }"
        : "=r"(a) : "l"(p));
    return a;
}
#define SW128(o) ((o) ^ (((o) >> 3) & 0x70))

__device__ __forceinline__ float eluf(float x){ return x > 0.f ? x : expm1f(x); }

__device__ __forceinline__ float fexp(float x){
    const float L2E   = 1.4426950408889634f;
    const float MAGIC = 12582912.0f;
    float t  = x * L2E;
    float kf = t + MAGIC;
    int   ki = __float_as_int(kf);
    float km = kf - MAGIC;
    float f  = t - km;
    float p  = 1.33335581e-3f;
    p = fmaf(p, f, 9.61812910e-3f);
    p = fmaf(p, f, 5.55041087e-2f);
    p = fmaf(p, f, 2.40226507e-1f);
    p = fmaf(p, f, 6.93147180e-1f);
    p = fmaf(p, f, 1.0f);
    return __int_as_float(__float_as_int(p) + (int)((unsigned)ki << 23));
}

__device__ __forceinline__ void ldsm4(uint32_t* r, uint32_t addr){
    asm volatile("ldmatrix.sync.aligned.m8n8.x4.shared.b16 {%0,%1,%2,%3}, [%4];"
        : "=r"(r[0]),"=r"(r[1]),"=r"(r[2]),"=r"(r[3]) : "r"(addr));
}
__device__ __forceinline__ void mma16816h(float* c, const uint32_t* a, const uint32_t* b){
    asm volatile("mma.sync.aligned.m16n8k16.row.col.f32.f16.f16.f32 "
        "{%0,%1,%2,%3}, {%4,%5,%6,%7}, {%8,%9}, {%0,%1,%2,%3};"
        : "+f"(c[0]),"+f"(c[1]),"+f"(c[2]),"+f"(c[3])
        : "r"(a[0]),"r"(a[1]),"r"(a[2]),"r"(a[3]), "r"(b[0]),"r"(b[1]));
}
__device__ __forceinline__ void cpasync16(uint32_t dst, const void* src){
    asm volatile("cp.async.cg.shared.global [%0], [%1], 16;" :: "r"(dst), "l"(src));
}
#define CP_COMMIT() asm volatile("cp.async.commit_group;" ::: "memory")
#define CP_WAIT0()  asm volatile("cp.async.wait_group 0;"  ::: "memory")
#define CP_WAIT1()  asm volatile("cp.async.wait_group 1;"  ::: "memory")

// ---------------- K0: merged prep (pack_adj + split_ch + split_WT) -------
// blocks [0,1024): pack_adj; [1024,1536): split_ch;
// [1536,1600): split W1 (K=128); [1600,1856): split W2 (K=512)
__global__ void prep_k(const int* __restrict__ adj, const float* __restrict__ chems,
                       const float* __restrict__ W1, const float* __restrict__ W2){
    __shared__ float ts[32][33];
    int b = blockIdx.x;
    int tid = threadIdx.x;
    if (b < 1024){
        int gwarp = (b*256 + tid) >> 5;
        int lane  = tid & 31;
        const int nwarps = 1024*256/32;
        for (int w = gwarp; w < N_*NW_; w += nwarps){
            int v = adj[(size_t)w*32 + lane];
            unsigned bits = __ballot_sync(0xffffffffu, v > 0);
            if (lane == 0) g_adjb[w] = bits;
        }
    } else if (b < 1536){
        size_t base = ((size_t)(b-1024)*256 + tid)*16;   // 16 floats per thread
        #pragma unroll
        for (int q=0;q<4;q++){
            float4 v = *(const float4*)(chems + base + q*4);
            __half2 h0 = __floats2half2_rn(v.x, v.y);
            __half2 h1 = __floats2half2_rn(v.z, v.w);
            uint2 o = make_uint2(*(uint32_t*)&h0, *(uint32_t*)&h1);
            *(uint2*)((char*)g_ch + (base + q*4)*2) = o;
        }
    } else {
        const float* W; __half* T; int K, bb;
        if (b < 1600){ W = W1; T = g_W1T; K = 128; bb = b - 1536; }
        else         { W = W2; T = g_W2T; K = 512; bb = b - 1600; }
        int kblks = K/32;
        int k0 = (bb % kblks)*32;
        int f0 = ((bb / kblks) & 3)*32;
        int h  = bb / (kblks*4);
        int tx = tid & 31, ty = tid >> 5;
        const float* Wh = W + (size_t)h*K*128;
        #pragma unroll
        for (int r=0;r<4;r++)
            ts[ty + r*8][tx] = Wh[(size_t)(k0 + ty + r*8)*128 + f0 + tx];
        __syncthreads();
        #pragma unroll
        for (int r=0;r<4;r++){
            int f = f0 + ty + r*8;
            float v = ts[tx][ty + r*8];
            T[((size_t)h*128 + f)*K + k0 + tx] = __float2half_rn(v);
        }
    }
}

// ---------------- K1: Wh = X @ W, fp16, double-buffered, fused epilogue --
#define GA    0
#define GB    32768
#define GBUF  65536
#define ETT   0
#define ERED  36864
#define SMEMG (131072 + 1024)

__global__ __launch_bounds__(256,1) void gemm_hmma(int stage, int K,
                                                   const float* __restrict__ avec)
{
    extern __shared__ char dsm[];
    uint32_t raw = smem_u32(dsm);
    uint32_t sb  = (raw + 1023) & ~1023u;
    char* bpp = dsm + (sb - raw);

    const __half *A, *BT;
    long aHeadStride;
    if (stage == 1){ A = g_ch; BT = g_W1T; aHeadStride = (long)N_*D_; }
    else           { A = g_x;  BT = g_W2T; aHeadStride = 0; }

    int h = blockIdx.y, m0 = blockIdx.x*128;
    int tid = threadIdx.x, lane = tid & 31, wid = tid >> 5;
    int wm = wid >> 2, wn = wid & 3;
    const char* pA = (const char*)(A + (size_t)h*aHeadStride + (size_t)m0*K);
    const char* pB = (const char*)(BT + (size_t)h*128*K);
    long rs = (long)K*2;

    float acc[4][4][4];
    #pragma unroll
    for (int a=0;a<4;a++)
        #pragma unroll
        for (int b=0;b<4;b++)
            #pragma unroll
            for (int c=0;c<4;c++) acc[a][b][c]=0.f;

    auto ldpart = [&](uint32_t dstBase, const char* g, long colByte){
        #pragma unroll
        for (int l=0;l<8;l++){
            int idx = tid + l*256;
            int row = idx >> 4;
            int s16 = idx & 15;
            uint32_t so = SW128((uint32_t)(row*128 + (s16&7)*16)) + (uint32_t)(s16>>3)*16384;
            cpasync16(sb + dstBase + so, g + (long)row*rs + colByte + s16*16);
        }
    };

    int nk = K >> 7;
    // prologue: chunk 0 into buffer 0
    ldpart(GA, pA, 0);
    ldpart(GB, pB, 0);
    CP_COMMIT();
    for (int kc = 0; kc < nk; ++kc){
        uint32_t cbuf = (uint32_t)(kc & 1) * GBUF;
        if (kc + 1 < nk){
            uint32_t nbuf = cbuf ^ GBUF;
            long cb = (long)(kc+1)*256;
            ldpart(nbuf + GA, pA, cb);
            ldpart(nbuf + GB, pB, cb);
            CP_COMMIT();
            CP_WAIT1();          // chunk kc resident; kc+1 in flight
        } else {
            CP_WAIT0();
        }
        __syncthreads();
        #pragma unroll
        for (int kt=0;kt<8;kt++){
            uint32_t subo = cbuf + (uint32_t)(kt>>2)*16384;
            uint32_t kb = (uint32_t)((kt&3)*32 + (lane>>4)*16);
            uint32_t bh[4][2];
            #pragma unroll
            for (int pp=0;pp<2;pp++){
                uint32_t off = SW128((uint32_t)((wn*32 + pp*16 + (lane&15))*128) + kb) + subo;
                uint32_t t0[4];
                ldsm4(t0, sb + GB + off);
                bh[pp*2  ][0]=t0[0]; bh[pp*2  ][1]=t0[2];
                bh[pp*2+1][0]=t0[1]; bh[pp*2+1][1]=t0[3];
            }
            #pragma unroll
            for (int mt=0;mt<4;mt++){
                uint32_t off = SW128((uint32_t)((wm*64 + mt*16 + (lane&15))*128) + kb) + subo;
                uint32_t ah[4];
                ldsm4(ah, sb + GA + off);
                #pragma unroll
                for (int nt=0;nt<4;nt++)
                    mma16816h(acc[mt][nt], ah, bh[nt]);
            }
        }
        __syncthreads();
    }

    // ---------------- fused epilogue ----------------
    __half* tT   = (__half*)(bpp + ETT);
    float*  sred = (float*)(bpp + ERED);
    const float* av = avec + h*2*D_;

    float sp[8], dp[8];
    #pragma unroll
    for (int i=0;i<8;i++){ sp[i]=0.f; dp[i]=0.f; }

    #pragma unroll
    for (int nt=0;nt<4;nt++){
        int fcol = wn*32 + nt*8 + (lane&3)*2;
        float as0 = av[fcol],       as1 = av[fcol+1];
        float ad0 = av[D_+fcol],    ad1 = av[D_+fcol+1];
        #pragma unroll
        for (int mt=0;mt<4;mt++){
            int r0l = wm*64 + mt*16 + (lane>>2);
            float c0 = acc[mt][nt][0], c1 = acc[mt][nt][1];
            float c2 = acc[mt][nt][2], c3 = acc[mt][nt][3];
            sp[mt*2  ] += c0*as0 + c1*as1;
            sp[mt*2+1] += c2*as0 + c3*as1;
            dp[mt*2  ] += c0*ad0 + c1*ad1;
            dp[mt*2+1] += c2*ad0 + c3*ad1;
            tT[(size_t)fcol*136     + r0l    ] = __float2half_rn(c0);
            tT[(size_t)(fcol+1)*136 + r0l    ] = __float2half_rn(c1);
            tT[(size_t)fcol*136     + r0l + 8] = __float2half_rn(c2);
            tT[(size_t)(fcol+1)*136 + r0l + 8] = __float2half_rn(c3);
        }
    }
    #pragma unroll
    for (int k=1;k<4;k<<=1){
        #pragma unroll
        for (int i=0;i<8;i++){
            sp[i] += __shfl_xor_sync(0xffffffffu, sp[i], k);
            dp[i] += __shfl_xor_sync(0xffffffffu, dp[i], k);
        }
    }
    if ((lane & 3) == 0){
        #pragma unroll
        for (int mt=0;mt<4;mt++){
            int r0l = wm*64 + mt*16 + (lane>>2);
            sred[0*512 + wn*128 + r0l    ] = sp[mt*2];
            sred[0*512 + wn*128 + r0l + 8] = sp[mt*2+1];
            sred[1*512 + wn*128 + r0l    ] = dp[mt*2];
            sred[1*512 + wn*128 + r0l + 8] = dp[mt*2+1];
        }
    }
    __syncthreads();
    if (tid < 128){
        float s = sred[0*512 + tid] + sred[0*512 + 128 + tid]
                + sred[0*512 + 256 + tid] + sred[0*512 + 384 + tid];
        float d = sred[1*512 + tid] + sred[1*512 + 128 + tid]
                + sred[1*512 + 256 + tid] + sred[1*512 + 384 + tid];
        int i = m0 + tid;
        g_EFs[h*N_+i] = make_float2(fexp(s), fexp(ALPHA_*s));
        g_EFd[h*N_+i] = make_float2(fexp(d), fexp(ALPHA_*d));
    }
    {
        int f = tid >> 1, half = tid & 1;
        const uint4* src = (const uint4*)((const char*)tT + (size_t)f*272 + half*128);
        uint4* dst = (uint4*)(g_whT + ((size_t)(h*D_ + f))*N_ + m0 + half*64);
        #pragma unroll
        for (int q=0;q<8;q++) dst[q] = src[q];
    }
}

// ---------------- K3: warp-specialized attn (R12 proven config) ----------
#define PB    0
#define WB    16384
#define BUFSZ 32768
#define OFF_L (2*BUFSZ)
#define SMEM_DYN (2*BUFSZ + 512 + 1024)

__global__ __launch_bounds__(512,1) void attn_hmma(float* __restrict__ out_ext, int stage) {
    extern __shared__ char dsm[];
    uint32_t raw = smem_u32(dsm);
    uint32_t sb  = (raw + 1023) & ~1023u;
    char* bp = dsm + (sb - raw);
    float* sml = (float*)(bp + OFF_L);

    int h = blockIdx.y, i0 = blockIdx.x*128;
    int tid = threadIdx.x, lane = tid & 31, wid = tid >> 5;
    bool producer = (wid >= 8);

    if (producer) {
        int ptid = tid - 256;
        int r = ptid >> 1, jh = ptid & 1;
        float2 efs = g_EFs[h*N_ + i0 + r];
        float Ei = efs.x, Fi = efs.y;
        const float2*   efd    = g_EFd + h*N_;
        const unsigned* adjrow = g_adjb + (size_t)(i0+r)*NW_;
        const char* whh = (const char*)(g_whT + (size_t)h*D_*N_);
        float rsum = 0.f;

        auto loadW = [&](uint32_t tb, int c){
            int j0 = c * 64;
            #pragma unroll
            for (int l=0;l<4;l++){
                int idx = ptid + l*256;
                int f = idx >> 3, seg = idx & 7;
                size_t go = (((size_t)f*N_ + j0) << 1) + (size_t)seg*16;
                uint32_t so = SW128((uint32_t)(f*128 + seg*16));
                cpasync16(sb + tb + WB + so, whh + go);
            }
            CP_COMMIT();
        };
        auto genP = [&](uint32_t tb, int c){
            int j0 = c * 64;
            unsigned w = adjrow[(j0>>5) + jh];
            const float4* efp = (const float4*)(efd + j0 + jh*32);
            uint32_t rb = (uint32_t)(r*128 + jh*64);
            #pragma unroll
            for (int q=0;q<16;q++){
                float4 e01 = efp[q];
                float p0 = fmaxf(Ei*e01.x, Fi*e01.y);
                float p1 = fmaxf(Ei*e01.z, Fi*e01.w);
                p0 = ((w>>(2*q  ))&1u) ? p0 : 0.f;
                p1 = ((w>>(2*q+1))&1u) ? p1 : 0.f;
                rsum += p0 + p1;
                __half2 hp = __floats2half2_rn(p0, p1);
                *(uint32_t*)(bp + tb + PB + SW128(rb + q*4)) = *(uint32_t*)&hp;
            }
        };

        loadW(0u, 0);
        genP(0u, 0);
        CP_WAIT0();
        __syncthreads();
        for (int c = 0; c < 64; ++c) {
            uint32_t nb = (uint32_t)(~c & 1) * BUFSZ;
            if (c < 63){
                loadW(nb, c+1);          // async first, hidden under genP
                genP(nb, c+1);
                CP_WAIT0();
            }
            __syncthreads();
        }
        float full = rsum + __shfl_xor_sync(0xffffffffu, rsum, 1);
        if (!(ptid & 1)) sml[r] = 1.0f / full;
        __syncthreads();
    } else {
        int wm = wid >> 2, wn = wid & 3;
        float acc[4][4][4];
        #pragma unroll
        for (int a=0;a<4;a++)
            #pragma unroll
            for (int b=0;b<4;b++)
                #pragma unroll
                for (int c=0;c<4;c++) acc[a][b][c]=0.f;

        __syncthreads();
        for (int c = 0; c < 64; ++c) {
            uint32_t tb = (uint32_t)(c & 1) * BUFSZ;
            #pragma unroll
            for (int kt=0;kt<4;kt++){
                uint32_t kb = (uint32_t)(kt*32 + (lane>>4)*16);
                uint32_t bh[4][2];
                #pragma unroll
                for (int pp=0;pp<2;pp++){
                    uint32_t off = SW128((uint32_t)((wn*32 + pp*16 + (lane&15))*128) + kb);
                    uint32_t t0[4];
                    ldsm4(t0, sb + tb + WB + off);
                    bh[pp*2  ][0]=t0[0]; bh[pp*2  ][1]=t0[2];
                    bh[pp*2+1][0]=t0[1]; bh[pp*2+1][1]=t0[3];
                }
                #pragma unroll
                for (int mt=0;mt<4;mt++){
                    uint32_t off = SW128((uint32_t)((wm*64 + mt*16 + (lane&15))*128) + kb);
                    uint32_t ah[4];
                    ldsm4(ah, sb + tb + PB + off);
                    #pragma unroll
                    for (int nt=0;nt<4;nt++)
                        mma16816h(acc[mt][nt], ah, bh[nt]);
                }
            }
            __syncthreads();
        }
        __syncthreads();                 // sml ready
        #pragma unroll
        for (int mt=0;mt<4;mt++){
            int r0 = wm*64 + mt*16 + (lane>>2);
            float il0 = sml[r0], il1 = sml[r0+8];
            #pragma unroll
            for (int nt=0;nt<4;nt++){
                int fcol = wn*32 + nt*8 + (lane&3)*2;
                float2 v0, v1;
                v0.x = eluf(acc[mt][nt][0]*il0);
                v0.y = eluf(acc[mt][nt][1]*il0);
                v1.x = eluf(acc[mt][nt][2]*il1);
                v1.y = eluf(acc[mt][nt][3]*il1);
                if (stage == 1){
                    size_t o0 = ((size_t)(i0+r0  )*KX_ + h*D_ + fcol);
                    size_t o1 = ((size_t)(i0+r0+8)*KX_ + h*D_ + fcol);
                    __half2 x0 = __floats2half2_rn(v0.x, v0.y);
                    __half2 x1 = __floats2half2_rn(v1.x, v1.y);
                    *(uint32_t*)((char*)g_x + o0*2) = *(uint32_t*)&x0;
                    *(uint32_t*)((char*)g_x + o1*2) = *(uint32_t*)&x1;
                } else {
                    *(float2*)(out_ext + (size_t)(i0+r0  )*KX_ + h*D_ + fcol) = v0;
                    *(float2*)(out_ext + (size_t)(i0+r0+8)*KX_ + h*D_ + fcol) = v1;
                }
            }
        }
    }
}

// ---------------- launch ----------------
extern "C" void kernel_launch(void* const* d_in, const int* in_sizes, int n_in,
                              void* d_out, int out_size) {
    const float* chems = (const float*)d_in[0];
    const int*   adj   = (const int*)  d_in[1];
    const float* W1    = (const float*)d_in[2];
    const float* a1    = (const float*)d_in[3];
    const float* W2    = (const float*)d_in[4];
    const float* a2    = (const float*)d_in[5];
    float* out = (float*)d_out;

    cudaFuncSetAttribute(attn_hmma, cudaFuncAttributeMaxDynamicSharedMemorySize, SMEM_DYN);
    cudaFuncSetAttribute(gemm_hmma, cudaFuncAttributeMaxDynamicSharedMemorySize, SMEMG);

    prep_k<<<1856, 256>>>(adj, chems, W1, W2);

    // stage 1 (gemm fuses Wh^T conversion + src/dst exp factors)
    gemm_hmma<<<dim3(N_/128, H_), 256, SMEMG>>>(1, 128, a1);
    attn_hmma<<<dim3(N_/128, H_), 512, SMEM_DYN>>>(nullptr, 1);

    // stage 2
    gemm_hmma<<<dim3(N_/128, H_), 256, SMEMG>>>(2, 512, a2);
    attn_hmma<<<dim3(N_/128, H_), 512, SMEM_DYN>>>(out, 2);
}